// round 1
// baseline (speedup 1.0000x reference)
#include <cuda_runtime.h>
#include <math.h>

// Problem constants
#define TOK 4096          // B * L = 2 * 2048
#define CDIM 384
#define LSEQ 2048
#define NB 2
#define DSTATE 16
#define DTRANK 24
#define DBC_W 56          // r + 2*ds

// ---------------- scratch (no cudaMalloc allowed) ----------------
__device__ float g_hln[TOK*CDIM];
__device__ float g_xz [TOK*768];
__device__ float g_xc [TOK*CDIM];
__device__ float g_dbc[TOK*DBC_W];
__device__ float g_dt [TOK*CDIM];
__device__ float g_y  [TOK*CDIM];
__device__ float g_y2 [TOK*CDIM];
__device__ float g_x1 [TOK*CDIM];
__device__ float g_h2 [TOK*CDIM];
__device__ float g_t1 [TOK*CDIM];
__device__ float g_wT [27*CDIM];

// ---------------- math helpers ----------------
__device__ __forceinline__ float siluf(float x){ return x / (1.f + __expf(-x)); }
__device__ __forceinline__ float geluf(float x){
    // JAX default gelu (approximate=True, tanh form)
    float x3 = x*x*x;
    return 0.5f*x*(1.f + tanhf(0.7978845608028654f*(x + 0.044715f*x3)));
}
__device__ __forceinline__ float softplusf(float x){
    // logaddexp(x, 0)
    return fmaxf(x, 0.f) + log1pf(__expf(-fabsf(x)));
}

// ---------------- LayerNorm over C=384 (block per row, 128 thr) ----------------
__global__ void ln_kernel(const float* __restrict__ x, const float* __restrict__ gw,
                          const float* __restrict__ bw, float* __restrict__ out){
    int row = blockIdx.x;
    int tid = threadIdx.x;
    const float* xr = x + (size_t)row*CDIM;
    float v0 = xr[tid], v1 = xr[tid+128], v2 = xr[tid+256];
    float s = v0+v1+v2;
    float q = v0*v0 + v1*v1 + v2*v2;
    #pragma unroll
    for (int m = 16; m; m >>= 1){
        s += __shfl_xor_sync(0xffffffffu, s, m);
        q += __shfl_xor_sync(0xffffffffu, q, m);
    }
    __shared__ float red[8];
    if ((tid & 31) == 0){ red[tid>>5] = s; red[4 + (tid>>5)] = q; }
    __syncthreads();
    s = red[0]+red[1]+red[2]+red[3];
    q = red[4]+red[5]+red[6]+red[7];
    float mean = s * (1.f/CDIM);
    float var  = q * (1.f/CDIM) - mean*mean;
    float r = rsqrtf(var + 1e-6f);
    float* orow = out + (size_t)row*CDIM;
    orow[tid]     = (v0-mean)*r*gw[tid]     + bw[tid];
    orow[tid+128] = (v1-mean)*r*gw[tid+128] + bw[tid+128];
    orow[tid+256] = (v2-mean)*r*gw[tid+256] + bw[tid+256];
}

// LN(y) * silu(z), z lives at xz[row*768 + 384 + c]
__global__ void ln_gate_kernel(const float* __restrict__ y, const float* __restrict__ xz,
                               const float* __restrict__ gw, const float* __restrict__ bw,
                               float* __restrict__ out){
    int row = blockIdx.x;
    int tid = threadIdx.x;
    const float* yr = y + (size_t)row*CDIM;
    const float* zr = xz + (size_t)row*768 + 384;
    float v0 = yr[tid], v1 = yr[tid+128], v2 = yr[tid+256];
    float s = v0+v1+v2;
    float q = v0*v0 + v1*v1 + v2*v2;
    #pragma unroll
    for (int m = 16; m; m >>= 1){
        s += __shfl_xor_sync(0xffffffffu, s, m);
        q += __shfl_xor_sync(0xffffffffu, q, m);
    }
    __shared__ float red[8];
    if ((tid & 31) == 0){ red[tid>>5] = s; red[4 + (tid>>5)] = q; }
    __syncthreads();
    s = red[0]+red[1]+red[2]+red[3];
    q = red[4]+red[5]+red[6]+red[7];
    float mean = s * (1.f/CDIM);
    float var  = q * (1.f/CDIM) - mean*mean;
    float r = rsqrtf(var + 1e-6f);
    float* orow = out + (size_t)row*CDIM;
    orow[tid]     = ((v0-mean)*r*gw[tid]     + bw[tid])     * siluf(zr[tid]);
    orow[tid+128] = ((v1-mean)*r*gw[tid+128] + bw[tid+128]) * siluf(zr[tid+128]);
    orow[tid+256] = ((v2-mean)*r*gw[tid+256] + bw[tid+256]) * siluf(zr[tid+256]);
}

// ---------------- conv weight transpose [c][k] -> [k][c] ----------------
__global__ void wtrans_kernel(const float* __restrict__ cw, float* __restrict__ wT){
    int i = blockIdx.x*256 + threadIdx.x;
    if (i < 27*CDIM){
        int c = i / 27, k = i % 27;
        wT[k*CDIM + c] = cw[i];
    }
}

// ---------------- depthwise 3x3x3 conv + bias + SiLU ----------------
// input = xin = first 384 cols of xz (row stride 768); output contiguous [TOK,384]
__global__ void conv_silu_kernel(const float* __restrict__ xz, const float* __restrict__ wT,
                                 const float* __restrict__ cb, float* __restrict__ out){
    int tok = blockIdx.x;        // 0..4095
    int c   = threadIdx.x;       // 0..383
    int b = tok >> 11;
    int l = tok & 2047;
    int dd = l >> 8, hh = (l >> 4) & 15, ww = l & 15;
    float acc = cb[c];
    #pragma unroll
    for (int kd = 0; kd < 3; kd++){
        int d2 = dd + kd - 1;
        if ((unsigned)d2 >= 8u) continue;
        #pragma unroll
        for (int kh = 0; kh < 3; kh++){
            int h2 = hh + kh - 1;
            if ((unsigned)h2 >= 16u) continue;
            #pragma unroll
            for (int kw = 0; kw < 3; kw++){
                int w2 = ww + kw - 1;
                if ((unsigned)w2 >= 16u) continue;
                int l2 = (d2 << 8) + (h2 << 4) + w2;
                float xv = __ldg(xz + ((size_t)(b*2048 + l2))*768 + c);
                float wv = __ldg(wT + ((kd*3+kh)*3+kw)*CDIM + c);
                acc = fmaf(xv, wv, acc);
            }
        }
    }
    out[(size_t)tok*CDIM + c] = siluf(acc);
}

// ---------------- SGEMM 128x128x8, 8x8 microtile, fused epilogue ----------------
// C[M,N] = epi(A[M,K](lda) @ B[K,N] + bias [+ res])
// epi: 0 plain, 1 softplus, 2 gelu, 3 add residual
__global__ void sgemm_kernel(const float* __restrict__ A, const float* __restrict__ B,
                             const float* __restrict__ bias, const float* __restrict__ res,
                             float* __restrict__ C,
                             int M, int N, int K, int lda, int epi){
    __shared__ __align__(16) float As[8][128];
    __shared__ __align__(16) float Bs[8][128];
    int tid  = threadIdx.x;
    int row0 = blockIdx.y * 128;
    int col0 = blockIdx.x * 128;
    int tx = tid & 15, ty = tid >> 4;

    float acc[8][8];
    #pragma unroll
    for (int i = 0; i < 8; i++)
        #pragma unroll
        for (int j = 0; j < 8; j++) acc[i][j] = 0.f;

    int arow = tid >> 1;
    int acol = (tid & 1) << 2;
    int brow = tid >> 5;
    int bcol = (tid & 31) << 2;

    const float* Aptr = A + (size_t)(row0 + arow)*lda + acol;
    int nt = K >> 3;   // K is always a multiple of 8 here (384 or 24)
    for (int kt = 0; kt < nt; kt++){
        float4 av = *reinterpret_cast<const float4*>(Aptr + kt*8);
        As[acol+0][arow] = av.x; As[acol+1][arow] = av.y;
        As[acol+2][arow] = av.z; As[acol+3][arow] = av.w;

        int gk = kt*8 + brow;
        int gn = col0 + bcol;
        float4 bv;
        if (gn + 3 < N){
            bv = *reinterpret_cast<const float4*>(B + (size_t)gk*N + gn);
        } else {
            bv.x = (gn+0 < N) ? B[(size_t)gk*N + gn+0] : 0.f;
            bv.y = (gn+1 < N) ? B[(size_t)gk*N + gn+1] : 0.f;
            bv.z = (gn+2 < N) ? B[(size_t)gk*N + gn+2] : 0.f;
            bv.w = (gn+3 < N) ? B[(size_t)gk*N + gn+3] : 0.f;
        }
        *reinterpret_cast<float4*>(&Bs[brow][bcol]) = bv;
        __syncthreads();

        #pragma unroll
        for (int k = 0; k < 8; k++){
            float a[8], b[8];
            *(float4*)&a[0] = *(const float4*)&As[k][ty*8];
            *(float4*)&a[4] = *(const float4*)&As[k][ty*8 + 4];
            *(float4*)&b[0] = *(const float4*)&Bs[k][tx*8];
            *(float4*)&b[4] = *(const float4*)&Bs[k][tx*8 + 4];
            #pragma unroll
            for (int i = 0; i < 8; i++)
                #pragma unroll
                for (int j = 0; j < 8; j++)
                    acc[i][j] = fmaf(a[i], b[j], acc[i][j]);
        }
        __syncthreads();
    }

    #pragma unroll
    for (int i = 0; i < 8; i++){
        int m = row0 + ty*8 + i;    // M == 4096 always, no guard needed
        #pragma unroll
        for (int j = 0; j < 8; j++){
            int n = col0 + tx*8 + j;
            if (n < N){
                float v = acc[i][j];
                if (bias) v += bias[n];
                if      (epi == 1) v = softplusf(v);
                else if (epi == 2) v = geluf(v);
                else if (epi == 3) v += res[(size_t)m*N + n];
                C[(size_t)m*N + n] = v;
            }
        }
    }
}

// ---------------- selective scan ----------------
// One 16-lane group per (b, d). Lane = state index s. dA computed on the fly.
// y[b,l,d] = sum_s carry[s]*Cm[b,l,s] + xin[b,l,d]*D_skip[d]
__global__ void scan_kernel(const float* __restrict__ dt, const float* __restrict__ xc,
                            const float* __restrict__ dbc, const float* __restrict__ A_log,
                            const float* __restrict__ Dsk, float* __restrict__ y){
    int tid = threadIdx.x;
    int g = tid >> 4;                 // 16 groups per 256-thread block
    int s = tid & 15;
    int idx = blockIdx.x * 16 + g;    // 0..767  (b*384 + d)
    int b = idx / CDIM;
    int d = idx % CDIM;

    float Ads   = -__expf(A_log[d*DSTATE + s]);
    float dskip = Dsk[d];
    float carry = 0.f;

    const float* dtp = dt  + (size_t)b*LSEQ*CDIM + d;
    const float* xp  = xc  + (size_t)b*LSEQ*CDIM + d;
    const float* bp  = dbc + (size_t)b*LSEQ*DBC_W + DTRANK + s;
    const float* cp  = dbc + (size_t)b*LSEQ*DBC_W + DTRANK + DSTATE + s;
    float* yp = y + (size_t)b*LSEQ*CDIM + d;

    #pragma unroll 4
    for (int l = 0; l < LSEQ; l++){
        float dtv = __ldg(dtp + (size_t)l*CDIM);
        float xv  = __ldg(xp  + (size_t)l*CDIM);
        float Bv  = __ldg(bp  + (size_t)l*DBC_W);
        float Cv  = __ldg(cp  + (size_t)l*DBC_W);
        float da  = __expf(dtv * Ads);
        carry = fmaf(da, carry, dtv * Bv * xv);
        float part = carry * Cv;
        part += __shfl_xor_sync(0xffffffffu, part, 1);
        part += __shfl_xor_sync(0xffffffffu, part, 2);
        part += __shfl_xor_sync(0xffffffffu, part, 4);
        part += __shfl_xor_sync(0xffffffffu, part, 8);
        if (s == 0) yp[(size_t)l*CDIM] = part + xv * dskip;
    }
}

// ---------------- launcher ----------------
extern "C" void kernel_launch(void* const* d_in, const int* in_sizes, int n_in,
                              void* d_out, int out_size){
    const float* x      = (const float*)d_in[0];
    const float* g1     = (const float*)d_in[1];
    const float* b1     = (const float*)d_in[2];
    const float* W_in   = (const float*)d_in[3];
    const float* b_in   = (const float*)d_in[4];
    const float* conv_w = (const float*)d_in[5];
    const float* conv_b = (const float*)d_in[6];
    const float* W_x    = (const float*)d_in[7];
    const float* W_dt   = (const float*)d_in[8];
    const float* b_dt   = (const float*)d_in[9];
    const float* A_log  = (const float*)d_in[10];
    const float* Dsk    = (const float*)d_in[11];
    const float* on_g   = (const float*)d_in[12];
    const float* on_b   = (const float*)d_in[13];
    const float* W_out  = (const float*)d_in[14];
    const float* b_out  = (const float*)d_in[15];
    const float* g2     = (const float*)d_in[16];
    const float* b2     = (const float*)d_in[17];
    const float* W1     = (const float*)d_in[18];
    const float* b1m    = (const float*)d_in[19];
    const float* W2     = (const float*)d_in[20];
    const float* b2m    = (const float*)d_in[21];
    float* out = (float*)d_out;

    float *hln, *xz, *xc, *dbc, *dt, *y, *y2, *x1, *h2, *t1, *wT;
    cudaGetSymbolAddress((void**)&hln, g_hln);
    cudaGetSymbolAddress((void**)&xz,  g_xz);
    cudaGetSymbolAddress((void**)&xc,  g_xc);
    cudaGetSymbolAddress((void**)&dbc, g_dbc);
    cudaGetSymbolAddress((void**)&dt,  g_dt);
    cudaGetSymbolAddress((void**)&y,   g_y);
    cudaGetSymbolAddress((void**)&y2,  g_y2);
    cudaGetSymbolAddress((void**)&x1,  g_x1);
    cudaGetSymbolAddress((void**)&h2,  g_h2);
    cudaGetSymbolAddress((void**)&t1,  g_t1);
    cudaGetSymbolAddress((void**)&wT,  g_wT);

    // 1) h = LN(x)
    ln_kernel<<<TOK, 128>>>(x, g1, b1, hln);
    // 2) xz = h @ W_in + b_in   [4096,768]
    sgemm_kernel<<<dim3(6,32), 256>>>(hln, W_in, b_in, nullptr, xz, TOK, 768, CDIM, CDIM, 0);
    // 3) depthwise conv + SiLU on xin branch
    wtrans_kernel<<<41, 256>>>(conv_w, wT);
    conv_silu_kernel<<<TOK, CDIM>>>(xz, wT, conv_b, xc);
    // 4) dbc = xc @ W_x          [4096,56]
    sgemm_kernel<<<dim3(1,32), 256>>>(xc, W_x, nullptr, nullptr, dbc, TOK, DBC_W, CDIM, CDIM, 0);
    // 5) dt = softplus(dbc[:, :24] @ W_dt + b_dt)   [4096,384]
    sgemm_kernel<<<dim3(3,32), 256>>>(dbc, W_dt, b_dt, nullptr, dt, TOK, CDIM, DTRANK, DBC_W, 1);
    // 6) selective scan -> y (+ D_skip*xin)
    scan_kernel<<<48, 256>>>(dt, xc, dbc, A_log, Dsk, y);
    // 7) y2 = LN(y)*silu(z)
    ln_gate_kernel<<<TOK, 128>>>(y, xz, on_g, on_b, y2);
    // 8) x1 = x + y2 @ W_out + b_out
    sgemm_kernel<<<dim3(3,32), 256>>>(y2, W_out, b_out, x, x1, TOK, CDIM, CDIM, CDIM, 3);
    // 9) h2 = LN(x1)
    ln_kernel<<<TOK, 128>>>(x1, g2, b2, h2);
    // 10) t1 = gelu(h2 @ W1 + b1m)
    sgemm_kernel<<<dim3(3,32), 256>>>(h2, W1, b1m, nullptr, t1, TOK, CDIM, CDIM, CDIM, 2);
    // 11) out = x1 + t1 @ W2 + b2m
    sgemm_kernel<<<dim3(3,32), 256>>>(t1, W2, b2m, x1, out, TOK, CDIM, CDIM, CDIM, 3);
}